// round 9
// baseline (speedup 1.0000x reference)
#include <cuda_runtime.h>
#include <cuda_fp16.h>
#include <cstdint>

#define BB   2
#define AA   512
#define TT   512
#define NF   128
#define NRBF 25
#define TILT 64
#define NTIL (TT / TILT)   // 8
#define TRBF (TILT * NRBF) // 1600

#define RSH 40    // sRbf row stride (halves)
#define HSH 136   // sH   row stride (halves)
#define WSH 140   // sW   row stride (halves; 280B, 8B-aligned rows)
#define WBUF (TILT * WSH)  // halves per W buffer

__device__ float    g_y[BB * AA * NF];
__device__ uint32_t g_w1ph[2 * 32 * 32];
__device__ uint32_t g_w2ph[8 * 32 * 32];

// shifted softplus: 1 MUFU + deg-6 poly log1p (|err|<7e-6), ln2 pre-subtracted
__device__ __forceinline__ float ssp(float v) {
    const float m = fmaxf(v, 0.0f);
    const float u = __expf(-fabsf(v));
    const float x = fmaf(2.0f, u, -1.0f);
    float p = -0.00027211f;
    p = fmaf(p, x, 0.00095152f);
    p = fmaf(p, x, -0.00305808f);
    p = fmaf(p, x, 0.01227896f);
    p = fmaf(p, x, -0.05556132f);
    p = fmaf(p, x, 0.33334183f);
    p = fmaf(p, x, -0.28768771f);
    return m + p;
}
__device__ __forceinline__ uint32_t smem_u32(const void* p) {
    uint32_t a;
    asm("{ .reg .u64 t; cvta.to.shared.u64 t, %1; cvt.u32.u64 %0, t; }"
        : "=r"(a) : "l"(p));
    return a;
}
__device__ __forceinline__ void mma16(float* c, const uint32_t* a,
                                      uint32_t b0, uint32_t b1) {
    asm volatile(
        "mma.sync.aligned.m16n8k16.row.col.f32.f16.f16.f32 "
        "{%0,%1,%2,%3}, {%4,%5,%6,%7}, {%8,%9}, {%0,%1,%2,%3};"
        : "+f"(c[0]), "+f"(c[1]), "+f"(c[2]), "+f"(c[3])
        : "r"(a[0]), "r"(a[1]), "r"(a[2]), "r"(a[3]), "r"(b0), "r"(b1));
}
__device__ __forceinline__ void ldmat4(uint32_t* r, uint32_t addr) {
    asm volatile(
        "ldmatrix.sync.aligned.m8n8.x4.shared.b16 {%0,%1,%2,%3}, [%4];"
        : "=r"(r[0]), "=r"(r[1]), "=r"(r[2]), "=r"(r[3]) : "r"(addr));
}
__device__ __forceinline__ uint32_t packh2(float lo, float hi) {
    __half2 h = __floats2half2_rn(lo, hi);
    return *reinterpret_cast<uint32_t*>(&h);
}

// ---------------------------------------------------------------------------
// fused prep + in2f
// ---------------------------------------------------------------------------
__global__ void prep_in2f_kernel(const float* __restrict__ x,
                                 const float* __restrict__ Win,
                                 const float* __restrict__ Wf1,
                                 const float* __restrict__ Wf2) {
    if (blockIdx.x < 512) {
        __shared__ float xs[2][NF];
        const int sub = threadIdx.x >> 7;
        const int f = threadIdx.x & 127;
        const int row = blockIdx.x * 2 + sub;
        xs[sub][f] = x[row * NF + f];
        __syncthreads();
        float acc = 0.0f;
#pragma unroll 8
        for (int i = 0; i < NF; ++i) acc += xs[sub][i] * Win[i * NF + f];
        g_y[row * NF + f] = acc;
    } else {
        const int idx = (blockIdx.x - 512) * 256 + threadIdx.x;
        if (idx < 2048) {
            const int ks = idx >> 10, rem = idx & 1023;
            const int lane = rem >> 5, i = rem & 31;
            const int j = i >> 1, r = i & 1;
            const int n = j * 8 + (lane >> 2);
            const int k0 = ks * 16 + r * 8 + (lane & 3) * 2;
            const float v0 = (k0 < NRBF) ? Wf1[k0 * NF + n] : 0.0f;
            const float v1 = (k0 + 1 < NRBF) ? Wf1[(k0 + 1) * NF + n] : 0.0f;
            const int off = (ks * 32 + lane) * 32 +
                            ((((i >> 2) ^ (lane & 7)) << 2) + (i & 3));
            g_w1ph[off] = packh2(v0, v1);
        } else if (idx < 2048 + 8192) {
            const int t = idx - 2048;
            const int ks = t >> 10, rem = t & 1023;
            const int lane = rem >> 5, i = rem & 31;
            const int j = i >> 1, r = i & 1;
            const int n = j * 8 + (lane >> 2);
            const int k0 = ks * 16 + r * 8 + (lane & 3) * 2;
            const int off = (ks * 32 + lane) * 32 +
                            ((((i >> 2) ^ (lane & 7)) << 2) + (i & 3));
            g_w2ph[off] = packh2(Wf2[k0 * NF + n], Wf2[(k0 + 1) * NF + n]);
        }
    }
}

// ---------------------------------------------------------------------------
// SMEM layout (bytes)
// ---------------------------------------------------------------------------
#define OFF_H     0          // 17408 (fp16 H)
#define OFF_W2P   17408      // 32768
#define OFF_RBF   50176      // 5120 (fp16 rbf)
#define OFF_W     55296      // 2 * 64*140*2 = 35840 (fp16 W, double buffer)
#define OFF_BF1   91136      // 512
#define OFF_BF2   91648      // 512
#define OFF_MASK  92160      // 512
#define OFF_NJ    92672      // 512
#define OFF_NK    93184      // 512
#define SMEM_BYTES 93696     // 91.5KB -> 2 blocks/SM

#define NTHREADS 256

__global__ __launch_bounds__(NTHREADS, 2)
void cfconv_mma(const float* __restrict__ r_ij,
                const float* __restrict__ pmask,
                const float* __restrict__ bf1, const float* __restrict__ bf2,
                const float* __restrict__ Wout, const float* __restrict__ bout,
                const int* __restrict__ nj, const int* __restrict__ nk,
                float* __restrict__ out) {
    extern __shared__ __align__(16) char smem[];
    __half*   sHh   = (__half*)(smem + OFF_H);
    uint32_t* sW2p  = (uint32_t*)(smem + OFF_W2P);
    __half*   sRbfH = (__half*)(smem + OFF_RBF);
    __half*   sWh   = (__half*)(smem + OFF_W);
    float* sBf1  = (float*)(smem + OFF_BF1);
    float* sBf2  = (float*)(smem + OFF_BF2);
    float* sMask = (float*)(smem + OFF_MASK);
    int*   sNj   = (int*)(smem + OFF_NJ);
    int*   sNk   = (int*)(smem + OFF_NK);
    float* sPart = (float*)(smem + OFF_W);          // post-loop aliases (buf0)
    float* sY    = (float*)(smem + OFF_W + 4096);
    float* sRed  = (float*)(smem + OFF_W + 4608);

    const int tid  = threadIdx.x;
    const int wid  = tid >> 5;
    const int lane = tid & 31;
    const int gid  = lane >> 2;
    const int l4   = lane & 3;
    const int wm   = wid >> 2;
    const int wn   = wid & 3;
    const int mbase = wm * 32;
    const int nb4   = wn * 2;
    const int f4    = lane * 4;
    const int a = blockIdx.x, b = blockIdx.y;
    const int ba = b * AA + a;
    const float* Yb = g_y + b * AA * NF;

    const int lrow  = (lane & 7) + ((lane >> 3) & 1) * 8;
    const int lkh   = ((lane >> 4) & 1) * 8;
    uint32_t addrR[2], addrH[2];
#pragma unroll
    for (int mt = 0; mt < 2; ++mt) {
        addrR[mt] = smem_u32(sRbfH + (mbase + mt * 16 + lrow) * RSH + lkh);
        addrH[mt] = smem_u32(sHh + (mbase + mt * 16 + lrow) * HSH + lkh);
    }

    // ---- prologue ----
    {
        const uint4* src = (const uint4*)g_w2ph;
        uint4* dst = (uint4*)sW2p;
        for (int i = tid; i < 2048; i += NTHREADS) dst[i] = src[i];
    }
    {
        uint32_t* z = (uint32_t*)sRbfH;
        for (int i = tid; i < (TILT * RSH) / 2; i += NTHREADS) z[i] = 0u;
    }
    if (tid < NF) { sBf1[tid] = bf1[tid]; sBf2[tid] = bf2[tid]; }

    uint32_t w1b[2][8];
#pragma unroll
    for (int ks = 0; ks < 2; ++ks) {
        const uint4* rowp = (const uint4*)g_w1ph + (ks * 32 + lane) * 8;
        uint4 q0 = __ldg(rowp + (nb4 ^ (lane & 7)));
        uint4 q1 = __ldg(rowp + ((nb4 + 1) ^ (lane & 7)));
        w1b[ks][0] = q0.x; w1b[ks][1] = q0.y; w1b[ks][2] = q0.z; w1b[ks][3] = q0.w;
        w1b[ks][4] = q1.x; w1b[ks][5] = q1.y; w1b[ks][6] = q1.z; w1b[ks][7] = q1.w;
    }
    __syncthreads();
    {   // stage tile 0
        const float* rsrc = r_ij + (long)ba * TT * NRBF;
        for (int i = tid; i < TRBF; i += NTHREADS) {
            const int t = i / NRBF, r = i - t * NRBF;
            sRbfH[t * RSH + r] = __float2half_rn(rsrc[i]);
        }
        if (tid < TILT) {
            const long p = (long)ba * TT + tid;
            sMask[tid] = pmask[p];
            sNj[tid] = nj[p];
            sNk[tid] = nk[p];
        }
    }
    __syncthreads();

    float4 accv = make_float4(0.f, 0.f, 0.f, 0.f);

    for (int tile = 0; tile < NTIL; ++tile) {
        const int cur = tile & 1;
        const int nxt = cur ^ 1;

        float C[2][4][4];
#pragma unroll
        for (int mt = 0; mt < 2; ++mt)
#pragma unroll
            for (int j = 0; j < 4; ++j)
#pragma unroll
                for (int q = 0; q < 4; ++q) C[mt][j][q] = 0.0f;

        // ---- GEMM1 ----
#pragma unroll
        for (int ks = 0; ks < 2; ++ks) {
            uint32_t A[2][4];
            ldmat4(A[0], addrR[0] + ks * 32);
            ldmat4(A[1], addrR[1] + ks * 32);
#pragma unroll
            for (int mt = 0; mt < 2; ++mt)
#pragma unroll
                for (int j = 0; j < 4; ++j)
                    mma16(C[mt][j], A[mt], w1b[ks][2 * j], w1b[ks][2 * j + 1]);
        }

        // ---- ssp(C + bf1) -> sH ----
#pragma unroll
        for (int mt = 0; mt < 2; ++mt)
#pragma unroll
            for (int j = 0; j < 4; ++j) {
                const int f0 = wn * 32 + j * 8 + l4 * 2;
                const float2 b1v = *(const float2*)(sBf1 + f0);
                const int r0 = mbase + mt * 16 + gid;
                *(__half2*)(sHh + r0 * HSH + f0) =
                    __floats2half2_rn(ssp(C[mt][j][0] + b1v.x),
                                      ssp(C[mt][j][1] + b1v.y));
                *(__half2*)(sHh + (r0 + 8) * HSH + f0) =
                    __floats2half2_rn(ssp(C[mt][j][2] + b1v.x),
                                      ssp(C[mt][j][3] + b1v.y));
            }

        // ---- prefetch next tile into registers ----
        float rstg[7];
        float stg_mk = 0.0f; int stg_j = 0, stg_k = 0;
        if (tile < NTIL - 1) {
            const float* rnext = r_ij + ((long)ba * TT + (tile + 1) * TILT) * NRBF;
#pragma unroll
            for (int q = 0; q < 7; ++q) {
                const int i = tid + q * NTHREADS;
                if (i < TRBF) rstg[q] = rnext[i];
            }
            if (tid < TILT) {
                const long p = (long)ba * TT + (tile + 1) * TILT + tid;
                stg_mk = pmask[p];
                stg_j = nj[p];
                stg_k = nk[p];
            }
        }
        __syncthreads();   // sync1: sH visible

        // ---- GEMM2 ----
#pragma unroll
        for (int mt = 0; mt < 2; ++mt)
#pragma unroll
            for (int j = 0; j < 4; ++j)
#pragma unroll
                for (int q = 0; q < 4; ++q) C[mt][j][q] = 0.0f;
#pragma unroll
        for (int ks = 0; ks < 8; ++ks) {
            uint32_t A[2][4];
            ldmat4(A[0], addrH[0] + ks * 32);
            ldmat4(A[1], addrH[1] + ks * 32);
            const uint4* rowp = (const uint4*)sW2p + (ks * 32 + lane) * 8;
            uint4 q0 = rowp[nb4 ^ (lane & 7)];
            uint4 q1 = rowp[(nb4 + 1) ^ (lane & 7)];
            uint32_t bu[8] = {q0.x, q0.y, q0.z, q0.w, q1.x, q1.y, q1.z, q1.w};
#pragma unroll
            for (int mt = 0; mt < 2; ++mt)
#pragma unroll
                for (int j = 0; j < 4; ++j)
                    mma16(C[mt][j], A[mt], bu[2 * j], bu[2 * j + 1]);
        }

        // ---- store (C + bf2) * mask as fp16 -> W buffer[cur] ----
        {
            __half* wb = sWh + cur * WBUF;
#pragma unroll
            for (int mt = 0; mt < 2; ++mt) {
                const int t0 = mbase + mt * 16 + gid;
                const float m0 = sMask[cur * TILT + t0];
                const float m1 = sMask[cur * TILT + t0 + 8];
#pragma unroll
                for (int j = 0; j < 4; ++j) {
                    const int f0 = wn * 32 + j * 8 + l4 * 2;
                    const float2 b2 = *(const float2*)(sBf2 + f0);
                    *(__half2*)(wb + t0 * WSH + f0) =
                        __floats2half2_rn((C[mt][j][0] + b2.x) * m0,
                                          (C[mt][j][1] + b2.y) * m0);
                    *(__half2*)(wb + (t0 + 8) * WSH + f0) =
                        __floats2half2_rn((C[mt][j][2] + b2.x) * m1,
                                          (C[mt][j][3] + b2.y) * m1);
                }
            }
        }

        // ---- store staged tile ----
        if (tile < NTIL - 1) {
#pragma unroll
            for (int q = 0; q < 7; ++q) {
                const int i = tid + q * NTHREADS;
                if (i < TRBF) {
                    const int t = i / NRBF, r = i - t * NRBF;
                    sRbfH[t * RSH + r] = __float2half_rn(rstg[q]);
                }
            }
            if (tid < TILT) {
                sMask[nxt * TILT + tid] = stg_mk;
                sNj[nxt * TILT + tid] = stg_j;
                sNk[nxt * TILT + tid] = stg_k;
            }
        }
        __syncthreads();   // sync2: W buffer complete, staged data visible

        // ---- row-coalesced epilogue: warp owns 8 t-rows, fp16 W ----
        {
            const __half* wb = sWh + cur * WBUF;
#pragma unroll
            for (int r = 0; r < 8; ++r) {
                const int t = wid * 8 + r;
                const float4 yj = *(const float4*)(Yb + sNj[cur * TILT + t] * NF + f4);
                const float4 yk = *(const float4*)(Yb + sNk[cur * TILT + t] * NF + f4);
                const uint2 wu = *(const uint2*)(wb + t * WSH + f4);
                const float2 wlo = __half22float2(*(const __half2*)&wu.x);
                const float2 whi = __half22float2(*(const __half2*)&wu.y);
                accv.x = fmaf(wlo.x, yj.x * yk.x, accv.x);
                accv.y = fmaf(wlo.y, yj.y * yk.y, accv.y);
                accv.z = fmaf(whi.x, yj.z * yk.z, accv.z);
                accv.w = fmaf(whi.y, yj.w * yk.w, accv.w);
            }
        }
    }

    __syncthreads();       // epilogue done everywhere before aliasing buf0
    // ---- cross-warp reduce ----
    *(float4*)(sPart + wid * NF + f4) = accv;
    __syncthreads();
    if (tid < NF) {
        float s = 0.0f;
#pragma unroll
        for (int w = 0; w < 8; ++w) s += sPart[w * NF + tid];
        sY[tid] = s;
    }
    __syncthreads();

    // ---- f2out ----
    {
        const int o = tid & 127;
        const int q = tid >> 7;
        float s = 0.0f;
        const float* Wp = Wout + q * 64 * NF + o;
#pragma unroll 8
        for (int f = 0; f < 64; ++f) s += sY[q * 64 + f] * Wp[f * NF];
        sRed[q * NF + o] = s;
    }
    __syncthreads();
    if (tid < NF)
        out[(long)ba * NF + tid] = ssp(sRed[tid] + sRed[NF + tid] + bout[tid]);
}

// ---------------------------------------------------------------------------
extern "C" void kernel_launch(void* const* d_in, const int* in_sizes, int n_in,
                              void* d_out, int out_size) {
    const float* x    = (const float*)d_in[0];
    const float* r_ij = (const float*)d_in[1];
    const float* mask = (const float*)d_in[2];
    const float* Wf1  = (const float*)d_in[3];
    const float* bf1  = (const float*)d_in[4];
    const float* Wf2  = (const float*)d_in[5];
    const float* bf2  = (const float*)d_in[6];
    const float* Win  = (const float*)d_in[7];
    const float* Wout = (const float*)d_in[8];
    const float* bout = (const float*)d_in[9];
    const int*   nj   = (const int*)d_in[10];
    const int*   nk   = (const int*)d_in[11];
    float* out = (float*)d_out;

    prep_in2f_kernel<<<552, 256>>>(x, Win, Wf1, Wf2);

    cudaFuncSetAttribute(cfconv_mma,
                         cudaFuncAttributeMaxDynamicSharedMemorySize, SMEM_BYTES);
    dim3 grid(AA, BB);
    cfconv_mma<<<grid, NTHREADS, SMEM_BYTES>>>(r_ij, mask, bf1, bf2,
                                               Wout, bout, nj, nk, out);
}

// round 10
// speedup vs baseline: 1.0298x; 1.0298x over previous
#include <cuda_runtime.h>
#include <cuda_fp16.h>
#include <cstdint>

#define BB   2
#define AA   512
#define TT   512
#define NF   128
#define NRBF 25
#define TILT 64
#define NTIL (TT / TILT)   // 8
#define TRBF (TILT * NRBF) // 1600

#define RSH 40    // sRbf row stride (halves)
#define HSH 136   // sH   row stride (halves)
#define WSH 140   // sW   row stride (halves)
#define WBUF (TILT * WSH)

__device__ float    g_y[BB * AA * NF];
__device__ uint32_t g_w1ph[2 * 32 * 32];
__device__ uint32_t g_w2ph[8 * 32 * 32];

// fp32 shifted softplus (used only in tiny f2out epilogue)
__device__ __forceinline__ float ssp(float v) {
    const float m = fmaxf(v, 0.0f);
    const float u = __expf(-fabsf(v));
    const float x = fmaf(2.0f, u, -1.0f);
    float p = -0.00027211f;
    p = fmaf(p, x, 0.00095152f);
    p = fmaf(p, x, -0.00305808f);
    p = fmaf(p, x, 0.01227896f);
    p = fmaf(p, x, -0.05556132f);
    p = fmaf(p, x, 0.33334183f);
    p = fmaf(p, x, -0.28768771f);
    return m + p;
}

// half2 ssp: exp in fp32 MUFU, deg-4 economized log1p poly in HFMA2.
// p(x) coeffs for ln(1+u)-ln2, x=2u-1, u in [0,1]; fp32 truncation err ~1.5e-4.
__device__ __forceinline__ __half2 ssp2(float c0, float c1) {
    const float u0 = __expf(-fabsf(c0));
    const float u1 = __expf(-fabsf(c1));
    const __half2 x = __floats2half2_rn(fmaf(2.0f, u0, -1.0f),
                                        fmaf(2.0f, u1, -1.0f));
    const __half2 v = __floats2half2_rn(c0, c1);
    const __half2 m = __hmax2(v, __float2half2_rn(0.0f));
    __half2 p = __float2half2_rn(-0.00342936f);
    p = __hfma2(p, x, __float2half2_rn(0.01337449f));
    p = __hfma2(p, x, __float2half2_rn(-0.05542695f));
    p = __hfma2(p, x, __float2half2_rn(0.33307613f));
    p = __hfma2(p, x, __float2half2_rn(-0.28768922f));   // 0.40545796 - ln2
    return __hadd2(m, p);
}
__device__ __forceinline__ uint32_t smem_u32(const void* p) {
    uint32_t a;
    asm("{ .reg .u64 t; cvta.to.shared.u64 t, %1; cvt.u32.u64 %0, t; }"
        : "=r"(a) : "l"(p));
    return a;
}
__device__ __forceinline__ void mma16(float* c, const uint32_t* a,
                                      uint32_t b0, uint32_t b1) {
    asm volatile(
        "mma.sync.aligned.m16n8k16.row.col.f32.f16.f16.f32 "
        "{%0,%1,%2,%3}, {%4,%5,%6,%7}, {%8,%9}, {%0,%1,%2,%3};"
        : "+f"(c[0]), "+f"(c[1]), "+f"(c[2]), "+f"(c[3])
        : "r"(a[0]), "r"(a[1]), "r"(a[2]), "r"(a[3]), "r"(b0), "r"(b1));
}
__device__ __forceinline__ void ldmat4(uint32_t* r, uint32_t addr) {
    asm volatile(
        "ldmatrix.sync.aligned.m8n8.x4.shared.b16 {%0,%1,%2,%3}, [%4];"
        : "=r"(r[0]), "=r"(r[1]), "=r"(r[2]), "=r"(r[3]) : "r"(addr));
}
__device__ __forceinline__ uint32_t packh2(float lo, float hi) {
    __half2 h = __floats2half2_rn(lo, hi);
    return *reinterpret_cast<uint32_t*>(&h);
}

// ---------------------------------------------------------------------------
// fused prep + in2f; bf1 folded into k=25 of w1 table
// ---------------------------------------------------------------------------
__global__ void prep_in2f_kernel(const float* __restrict__ x,
                                 const float* __restrict__ Win,
                                 const float* __restrict__ Wf1,
                                 const float* __restrict__ Wf2,
                                 const float* __restrict__ bf1) {
    if (blockIdx.x < 512) {
        __shared__ float xs[2][NF];
        const int sub = threadIdx.x >> 7;
        const int f = threadIdx.x & 127;
        const int row = blockIdx.x * 2 + sub;
        xs[sub][f] = x[row * NF + f];
        __syncthreads();
        float acc = 0.0f;
#pragma unroll 8
        for (int i = 0; i < NF; ++i) acc += xs[sub][i] * Win[i * NF + f];
        g_y[row * NF + f] = acc;
    } else {
        const int idx = (blockIdx.x - 512) * 256 + threadIdx.x;
        if (idx < 2048) {
            const int ks = idx >> 10, rem = idx & 1023;
            const int lane = rem >> 5, i = rem & 31;
            const int j = i >> 1, r = i & 1;
            const int n = j * 8 + (lane >> 2);
            const int k0 = ks * 16 + r * 8 + (lane & 3) * 2;
            const float v0 = (k0 < NRBF) ? Wf1[k0 * NF + n]
                           : (k0 == NRBF ? bf1[n] : 0.0f);
            const float v1 = (k0 + 1 < NRBF) ? Wf1[(k0 + 1) * NF + n]
                           : (k0 + 1 == NRBF ? bf1[n] : 0.0f);
            const int off = (ks * 32 + lane) * 32 +
                            ((((i >> 2) ^ (lane & 7)) << 2) + (i & 3));
            g_w1ph[off] = packh2(v0, v1);
        } else if (idx < 2048 + 8192) {
            const int t = idx - 2048;
            const int ks = t >> 10, rem = t & 1023;
            const int lane = rem >> 5, i = rem & 31;
            const int j = i >> 1, r = i & 1;
            const int n = j * 8 + (lane >> 2);
            const int k0 = ks * 16 + r * 8 + (lane & 3) * 2;
            const int off = (ks * 32 + lane) * 32 +
                            ((((i >> 2) ^ (lane & 7)) << 2) + (i & 3));
            g_w2ph[off] = packh2(Wf2[k0 * NF + n], Wf2[(k0 + 1) * NF + n]);
        }
    }
}

// ---------------------------------------------------------------------------
// SMEM layout (bytes)
// ---------------------------------------------------------------------------
#define OFF_H     0          // 17408
#define OFF_W2P   17408      // 32768
#define OFF_RBF   50176      // 5120
#define OFF_W     55296      // 35840 (fp16 W double buffer)
#define OFF_BF2   91136      // 512
#define OFF_MASK  91648      // 512
#define OFF_NJ    92160      // 512
#define OFF_NK    92672      // 512
#define SMEM_BYTES 93184

#define NTHREADS 256

__global__ __launch_bounds__(NTHREADS, 2)
void cfconv_mma(const float* __restrict__ r_ij,
                const float* __restrict__ pmask,
                const float* __restrict__ bf2,
                const float* __restrict__ Wout, const float* __restrict__ bout,
                const int* __restrict__ nj, const int* __restrict__ nk,
                float* __restrict__ out) {
    extern __shared__ __align__(16) char smem[];
    __half*   sHh   = (__half*)(smem + OFF_H);
    uint32_t* sW2p  = (uint32_t*)(smem + OFF_W2P);
    __half*   sRbfH = (__half*)(smem + OFF_RBF);
    __half*   sWh   = (__half*)(smem + OFF_W);
    float* sBf2  = (float*)(smem + OFF_BF2);
    float* sMask = (float*)(smem + OFF_MASK);
    int*   sNj   = (int*)(smem + OFF_NJ);
    int*   sNk   = (int*)(smem + OFF_NK);
    float* sPart = (float*)(smem + OFF_W);
    float* sY    = (float*)(smem + OFF_W + 4096);
    float* sRed  = (float*)(smem + OFF_W + 4608);

    const int tid  = threadIdx.x;
    const int wid  = tid >> 5;
    const int lane = tid & 31;
    const int gid  = lane >> 2;
    const int l4   = lane & 3;
    const int wm   = wid >> 2;
    const int wn   = wid & 3;
    const int mbase = wm * 32;
    const int nb4   = wn * 2;
    const int f4    = lane * 4;
    const int a = blockIdx.x, b = blockIdx.y;
    const int ba = b * AA + a;
    const float* Yb = g_y + b * AA * NF;

    const int lrow  = (lane & 7) + ((lane >> 3) & 1) * 8;
    const int lkh   = ((lane >> 4) & 1) * 8;
    uint32_t addrR[2], addrH[2];
#pragma unroll
    for (int mt = 0; mt < 2; ++mt) {
        addrR[mt] = smem_u32(sRbfH + (mbase + mt * 16 + lrow) * RSH + lkh);
        addrH[mt] = smem_u32(sHh + (mbase + mt * 16 + lrow) * HSH + lkh);
    }

    // ---- prologue ----
    {
        const uint4* src = (const uint4*)g_w2ph;
        uint4* dst = (uint4*)sW2p;
        for (int i = tid; i < 2048; i += NTHREADS) dst[i] = src[i];
    }
    {
        uint32_t* z = (uint32_t*)sRbfH;
        for (int i = tid; i < (TILT * RSH) / 2; i += NTHREADS) z[i] = 0u;
    }
    if (tid < NF) sBf2[tid] = bf2[tid];

    uint32_t w1b[2][8];
#pragma unroll
    for (int ks = 0; ks < 2; ++ks) {
        const uint4* rowp = (const uint4*)g_w1ph + (ks * 32 + lane) * 8;
        uint4 q0 = __ldg(rowp + (nb4 ^ (lane & 7)));
        uint4 q1 = __ldg(rowp + ((nb4 + 1) ^ (lane & 7)));
        w1b[ks][0] = q0.x; w1b[ks][1] = q0.y; w1b[ks][2] = q0.z; w1b[ks][3] = q0.w;
        w1b[ks][4] = q1.x; w1b[ks][5] = q1.y; w1b[ks][6] = q1.z; w1b[ks][7] = q1.w;
    }
    __syncthreads();      // rbf zeros visible
    {   // bias column (k=25 of rbf = 1.0) + stage tile 0
        if (tid < TILT) sRbfH[tid * RSH + NRBF] = __float2half_rn(1.0f);
        const float* rsrc = r_ij + (long)ba * TT * NRBF;
        for (int i = tid; i < TRBF; i += NTHREADS) {
            const int t = i / NRBF, r = i - t * NRBF;
            sRbfH[t * RSH + r] = __float2half_rn(rsrc[i]);
        }
        if (tid < TILT) {
            const long p = (long)ba * TT + tid;
            sMask[tid] = pmask[p];
            sNj[tid] = nj[p];
            sNk[tid] = nk[p];
        }
    }
    __syncthreads();

    float4 acc0 = make_float4(0.f, 0.f, 0.f, 0.f);
    float4 acc1 = make_float4(0.f, 0.f, 0.f, 0.f);

    for (int tile = 0; tile < NTIL; ++tile) {
        const int cur = tile & 1;
        const int nxt = cur ^ 1;

        float C[2][4][4];
#pragma unroll
        for (int mt = 0; mt < 2; ++mt)
#pragma unroll
            for (int j = 0; j < 4; ++j)
#pragma unroll
                for (int q = 0; q < 4; ++q) C[mt][j][q] = 0.0f;

        // ---- GEMM1 (bf1 folded via k=25 bias column) ----
#pragma unroll
        for (int ks = 0; ks < 2; ++ks) {
            uint32_t A[2][4];
            ldmat4(A[0], addrR[0] + ks * 32);
            ldmat4(A[1], addrR[1] + ks * 32);
#pragma unroll
            for (int mt = 0; mt < 2; ++mt)
#pragma unroll
                for (int j = 0; j < 4; ++j)
                    mma16(C[mt][j], A[mt], w1b[ks][2 * j], w1b[ks][2 * j + 1]);
        }

        // ---- ssp2(C) -> sH (half2 pipeline) ----
#pragma unroll
        for (int mt = 0; mt < 2; ++mt)
#pragma unroll
            for (int j = 0; j < 4; ++j) {
                const int f0 = wn * 32 + j * 8 + l4 * 2;
                const int r0 = mbase + mt * 16 + gid;
                *(__half2*)(sHh + r0 * HSH + f0) = ssp2(C[mt][j][0], C[mt][j][1]);
                *(__half2*)(sHh + (r0 + 8) * HSH + f0) = ssp2(C[mt][j][2], C[mt][j][3]);
            }

        // ---- prefetch next tile into registers ----
        float rstg[7];
        float stg_mk = 0.0f; int stg_j = 0, stg_k = 0;
        if (tile < NTIL - 1) {
            const float* rnext = r_ij + ((long)ba * TT + (tile + 1) * TILT) * NRBF;
#pragma unroll
            for (int q = 0; q < 7; ++q) {
                const int i = tid + q * NTHREADS;
                if (i < TRBF) rstg[q] = rnext[i];
            }
            if (tid < TILT) {
                const long p = (long)ba * TT + (tile + 1) * TILT + tid;
                stg_mk = pmask[p];
                stg_j = nj[p];
                stg_k = nk[p];
            }
        }
        __syncthreads();   // sync1: sH visible

        // ---- GEMM2 ----
#pragma unroll
        for (int mt = 0; mt < 2; ++mt)
#pragma unroll
            for (int j = 0; j < 4; ++j)
#pragma unroll
                for (int q = 0; q < 4; ++q) C[mt][j][q] = 0.0f;
#pragma unroll
        for (int ks = 0; ks < 8; ++ks) {
            uint32_t A[2][4];
            ldmat4(A[0], addrH[0] + ks * 32);
            ldmat4(A[1], addrH[1] + ks * 32);
            const uint4* rowp = (const uint4*)sW2p + (ks * 32 + lane) * 8;
            uint4 q0 = rowp[nb4 ^ (lane & 7)];
            uint4 q1 = rowp[(nb4 + 1) ^ (lane & 7)];
            uint32_t bu[8] = {q0.x, q0.y, q0.z, q0.w, q1.x, q1.y, q1.z, q1.w};
#pragma unroll
            for (int mt = 0; mt < 2; ++mt)
#pragma unroll
                for (int j = 0; j < 4; ++j)
                    mma16(C[mt][j], A[mt], bu[2 * j], bu[2 * j + 1]);
        }

        // ---- store (C + bf2) * mask as fp16 -> W buffer[cur] ----
        {
            __half* wb = sWh + cur * WBUF;
#pragma unroll
            for (int mt = 0; mt < 2; ++mt) {
                const int t0 = mbase + mt * 16 + gid;
                const float m0 = sMask[cur * TILT + t0];
                const float m1 = sMask[cur * TILT + t0 + 8];
#pragma unroll
                for (int j = 0; j < 4; ++j) {
                    const int f0 = wn * 32 + j * 8 + l4 * 2;
                    const float2 b2 = *(const float2*)(sBf2 + f0);
                    *(__half2*)(wb + t0 * WSH + f0) =
                        __floats2half2_rn((C[mt][j][0] + b2.x) * m0,
                                          (C[mt][j][1] + b2.y) * m0);
                    *(__half2*)(wb + (t0 + 8) * WSH + f0) =
                        __floats2half2_rn((C[mt][j][2] + b2.x) * m1,
                                          (C[mt][j][3] + b2.y) * m1);
                }
            }
        }

        // ---- store staged tile ----
        if (tile < NTIL - 1) {
#pragma unroll
            for (int q = 0; q < 7; ++q) {
                const int i = tid + q * NTHREADS;
                if (i < TRBF) {
                    const int t = i / NRBF, r = i - t * NRBF;
                    sRbfH[t * RSH + r] = __float2half_rn(rstg[q]);
                }
            }
            if (tid < TILT) {
                sMask[nxt * TILT + tid] = stg_mk;
                sNj[nxt * TILT + tid] = stg_j;
                sNk[nxt * TILT + tid] = stg_k;
            }
        }
        __syncthreads();   // sync2

        // ---- row-coalesced epilogue, 2 accumulator chains ----
        {
            const __half* wb = sWh + cur * WBUF;
#pragma unroll
            for (int r = 0; r < 8; r += 2) {
#pragma unroll
                for (int h = 0; h < 2; ++h) {
                    const int t = wid * 8 + r + h;
                    const float4 yj = *(const float4*)(Yb + sNj[cur * TILT + t] * NF + f4);
                    const float4 yk = *(const float4*)(Yb + sNk[cur * TILT + t] * NF + f4);
                    const uint2 wu = *(const uint2*)(wb + t * WSH + f4);
                    const float2 wlo = __half22float2(*(const __half2*)&wu.x);
                    const float2 whi = __half22float2(*(const __half2*)&wu.y);
                    float4& av = h ? acc1 : acc0;
                    av.x = fmaf(wlo.x, yj.x * yk.x, av.x);
                    av.y = fmaf(wlo.y, yj.y * yk.y, av.y);
                    av.z = fmaf(whi.x, yj.z * yk.z, av.z);
                    av.w = fmaf(whi.y, yj.w * yk.w, av.w);
                }
            }
        }
    }

    __syncthreads();
    // ---- cross-warp reduce ----
    {
        float4 accv = make_float4(acc0.x + acc1.x, acc0.y + acc1.y,
                                  acc0.z + acc1.z, acc0.w + acc1.w);
        *(float4*)(sPart + wid * NF + f4) = accv;
    }
    __syncthreads();
    if (tid < NF) {
        float s = 0.0f;
#pragma unroll
        for (int w = 0; w < 8; ++w) s += sPart[w * NF + tid];
        sY[tid] = s;
    }
    __syncthreads();

    // ---- f2out ----
    {
        const int o = tid & 127;
        const int q = tid >> 7;
        float s = 0.0f;
        const float* Wp = Wout + q * 64 * NF + o;
#pragma unroll 8
        for (int f = 0; f < 64; ++f) s += sY[q * 64 + f] * Wp[f * NF];
        sRed[q * NF + o] = s;
    }
    __syncthreads();
    if (tid < NF)
        out[(long)ba * NF + tid] = ssp(sRed[tid] + sRed[NF + tid] + bout[tid]);
}

// ---------------------------------------------------------------------------
extern "C" void kernel_launch(void* const* d_in, const int* in_sizes, int n_in,
                              void* d_out, int out_size) {
    const float* x    = (const float*)d_in[0];
    const float* r_ij = (const float*)d_in[1];
    const float* mask = (const float*)d_in[2];
    const float* Wf1  = (const float*)d_in[3];
    const float* bf1  = (const float*)d_in[4];
    const float* Wf2  = (const float*)d_in[5];
    const float* bf2  = (const float*)d_in[6];
    const float* Win  = (const float*)d_in[7];
    const float* Wout = (const float*)d_in[8];
    const float* bout = (const float*)d_in[9];
    const int*   nj   = (const int*)d_in[10];
    const int*   nk   = (const int*)d_in[11];
    float* out = (float*)d_out;

    prep_in2f_kernel<<<552, 256>>>(x, Win, Wf1, Wf2, bf1);

    cudaFuncSetAttribute(cfconv_mma,
                         cudaFuncAttributeMaxDynamicSharedMemorySize, SMEM_BYTES);
    dim3 grid(AA, BB);
    cfconv_mma<<<grid, NTHREADS, SMEM_BYTES>>>(r_ij, mask, bf2,
                                               Wout, bout, nj, nk, out);
}

// round 11
// speedup vs baseline: 1.0596x; 1.0289x over previous
#include <cuda_runtime.h>
#include <cuda_fp16.h>
#include <cstdint>

#define BB   2
#define AA   512
#define TT   512
#define NF   128
#define NRBF 25
#define TILT 64
#define NTIL (TT / TILT)   // 8
#define TRBF (TILT * NRBF) // 1600

#define RSH 40    // sRbf row stride (halves)
#define HSH 136   // sH   row stride (halves)
#define WSH 140   // sW   row stride (halves)
#define WBUF (TILT * WSH)

__device__ __half2  g_y2[BB * AA * NF / 2];   // fp16 y (L1-resident gather table)
__device__ uint32_t g_w1ph[2 * 32 * 32];
__device__ uint32_t g_w2ph[8 * 32 * 32];

// fp32 shifted softplus (tiny f2out epilogue)
__device__ __forceinline__ float ssp(float v) {
    const float m = fmaxf(v, 0.0f);
    const float u = __expf(-fabsf(v));
    const float x = fmaf(2.0f, u, -1.0f);
    float p = -0.00342936f;
    p = fmaf(p, x, 0.01337449f);
    p = fmaf(p, x, -0.05542695f);
    p = fmaf(p, x, 0.33307613f);
    p = fmaf(p, x, -0.28768922f);   // 0.40545796 - ln2
    return m + p;
}

// pairwise ssp: fp32 deg-4 poly (err ~6e-5), single fp16 rounding at the pack
__device__ __forceinline__ __half2 ssp2(float c0, float c1) {
    return __floats2half2_rn(ssp(c0), ssp(c1));
}
__device__ __forceinline__ uint32_t smem_u32(const void* p) {
    uint32_t a;
    asm("{ .reg .u64 t; cvta.to.shared.u64 t, %1; cvt.u32.u64 %0, t; }"
        : "=r"(a) : "l"(p));
    return a;
}
__device__ __forceinline__ void mma16(float* c, const uint32_t* a,
                                      uint32_t b0, uint32_t b1) {
    asm volatile(
        "mma.sync.aligned.m16n8k16.row.col.f32.f16.f16.f32 "
        "{%0,%1,%2,%3}, {%4,%5,%6,%7}, {%8,%9}, {%0,%1,%2,%3};"
        : "+f"(c[0]), "+f"(c[1]), "+f"(c[2]), "+f"(c[3])
        : "r"(a[0]), "r"(a[1]), "r"(a[2]), "r"(a[3]), "r"(b0), "r"(b1));
}
__device__ __forceinline__ void ldmat4(uint32_t* r, uint32_t addr) {
    asm volatile(
        "ldmatrix.sync.aligned.m8n8.x4.shared.b16 {%0,%1,%2,%3}, [%4];"
        : "=r"(r[0]), "=r"(r[1]), "=r"(r[2]), "=r"(r[3]) : "r"(addr));
}
__device__ __forceinline__ uint32_t packh2(float lo, float hi) {
    __half2 h = __floats2half2_rn(lo, hi);
    return *reinterpret_cast<uint32_t*>(&h);
}

// ---------------------------------------------------------------------------
// fused prep + in2f (y stored fp16); bf1 folded into k=25 of w1 table
// blocks 0..255: in2f (4 rows each); blocks 256..295: weight tables
// ---------------------------------------------------------------------------
__global__ void prep_in2f_kernel(const float* __restrict__ x,
                                 const float* __restrict__ Win,
                                 const float* __restrict__ Wf1,
                                 const float* __restrict__ Wf2,
                                 const float* __restrict__ bf1) {
    if (blockIdx.x < 256) {
        __shared__ float xs[4][NF];
        const int row4 = blockIdx.x * 4;
        for (int i = threadIdx.x; i < 4 * NF; i += 256)
            xs[i >> 7][i & 127] = x[(row4 + (i >> 7)) * NF + (i & 127)];
        __syncthreads();
        const int sub = threadIdx.x >> 6;        // 0..3
        const int f0 = (threadIdx.x & 63) * 2;
        float a0 = 0.0f, a1 = 0.0f;
#pragma unroll 8
        for (int i = 0; i < NF; ++i) {
            a0 += xs[sub][i] * Win[i * NF + f0];
            a1 += xs[sub][i] * Win[i * NF + f0 + 1];
        }
        g_y2[((row4 + sub) * NF + f0) >> 1] = __floats2half2_rn(a0, a1);
    } else {
        const int idx = (blockIdx.x - 256) * 256 + threadIdx.x;
        if (idx < 2048) {
            const int ks = idx >> 10, rem = idx & 1023;
            const int lane = rem >> 5, i = rem & 31;
            const int j = i >> 1, r = i & 1;
            const int n = j * 8 + (lane >> 2);
            const int k0 = ks * 16 + r * 8 + (lane & 3) * 2;
            const float v0 = (k0 < NRBF) ? Wf1[k0 * NF + n]
                           : (k0 == NRBF ? bf1[n] : 0.0f);
            const float v1 = (k0 + 1 < NRBF) ? Wf1[(k0 + 1) * NF + n]
                           : (k0 + 1 == NRBF ? bf1[n] : 0.0f);
            const int off = (ks * 32 + lane) * 32 +
                            ((((i >> 2) ^ (lane & 7)) << 2) + (i & 3));
            g_w1ph[off] = packh2(v0, v1);
        } else if (idx < 2048 + 8192) {
            const int t = idx - 2048;
            const int ks = t >> 10, rem = t & 1023;
            const int lane = rem >> 5, i = rem & 31;
            const int j = i >> 1, r = i & 1;
            const int n = j * 8 + (lane >> 2);
            const int k0 = ks * 16 + r * 8 + (lane & 3) * 2;
            const int off = (ks * 32 + lane) * 32 +
                            ((((i >> 2) ^ (lane & 7)) << 2) + (i & 3));
            g_w2ph[off] = packh2(Wf2[k0 * NF + n], Wf2[(k0 + 1) * NF + n]);
        }
    }
}

// ---------------------------------------------------------------------------
// SMEM layout (bytes)
// ---------------------------------------------------------------------------
#define OFF_H     0          // 17408
#define OFF_W2P   17408      // 32768
#define OFF_RBF   50176      // 5120
#define OFF_W     55296      // 35840 (fp16 W double buffer)
#define OFF_BF2   91136      // 512
#define OFF_MASK  91648      // 512
#define OFF_NJ    92160      // 512
#define OFF_NK    92672      // 512
#define SMEM_BYTES 93184

#define NTHREADS 256

__global__ __launch_bounds__(NTHREADS, 2)
void cfconv_mma(const float* __restrict__ r_ij,
                const float* __restrict__ pmask,
                const float* __restrict__ bf2,
                const float* __restrict__ Wout, const float* __restrict__ bout,
                const int* __restrict__ nj, const int* __restrict__ nk,
                float* __restrict__ out) {
    extern __shared__ __align__(16) char smem[];
    __half*   sHh   = (__half*)(smem + OFF_H);
    uint32_t* sW2p  = (uint32_t*)(smem + OFF_W2P);
    __half*   sRbfH = (__half*)(smem + OFF_RBF);
    __half*   sWh   = (__half*)(smem + OFF_W);
    float* sBf2  = (float*)(smem + OFF_BF2);
    float* sMask = (float*)(smem + OFF_MASK);
    int*   sNj   = (int*)(smem + OFF_NJ);
    int*   sNk   = (int*)(smem + OFF_NK);
    float* sPart = (float*)(smem + OFF_W);
    float* sY    = (float*)(smem + OFF_W + 4096);
    float* sRed  = (float*)(smem + OFF_W + 4608);

    const int tid  = threadIdx.x;
    const int wid  = tid >> 5;
    const int lane = tid & 31;
    const int gid  = lane >> 2;
    const int l4   = lane & 3;
    const int wm   = wid >> 2;
    const int wn   = wid & 3;
    const int mbase = wm * 32;
    const int nb4   = wn * 2;
    const int f4    = lane * 4;
    const int a = blockIdx.x, b = blockIdx.y;
    const int ba = b * AA + a;
    const __half* Yb = (const __half*)g_y2 + (long)b * AA * NF;

    const int lrow  = (lane & 7) + ((lane >> 3) & 1) * 8;
    const int lkh   = ((lane >> 4) & 1) * 8;
    uint32_t addrR[2], addrH[2];
#pragma unroll
    for (int mt = 0; mt < 2; ++mt) {
        addrR[mt] = smem_u32(sRbfH + (mbase + mt * 16 + lrow) * RSH + lkh);
        addrH[mt] = smem_u32(sHh + (mbase + mt * 16 + lrow) * HSH + lkh);
    }

    // ---- prologue ----
    {
        const uint4* src = (const uint4*)g_w2ph;
        uint4* dst = (uint4*)sW2p;
        for (int i = tid; i < 2048; i += NTHREADS) dst[i] = src[i];
    }
    {
        uint32_t* z = (uint32_t*)sRbfH;
        for (int i = tid; i < (TILT * RSH) / 2; i += NTHREADS) z[i] = 0u;
    }
    if (tid < NF) sBf2[tid] = bf2[tid];

    uint32_t w1b[2][8];
#pragma unroll
    for (int ks = 0; ks < 2; ++ks) {
        const uint4* rowp = (const uint4*)g_w1ph + (ks * 32 + lane) * 8;
        uint4 q0 = __ldg(rowp + (nb4 ^ (lane & 7)));
        uint4 q1 = __ldg(rowp + ((nb4 + 1) ^ (lane & 7)));
        w1b[ks][0] = q0.x; w1b[ks][1] = q0.y; w1b[ks][2] = q0.z; w1b[ks][3] = q0.w;
        w1b[ks][4] = q1.x; w1b[ks][5] = q1.y; w1b[ks][6] = q1.z; w1b[ks][7] = q1.w;
    }
    __syncthreads();      // rbf zeros visible
    {   // bias column (k=25 of rbf = 1.0) + stage tile 0
        if (tid < TILT) sRbfH[tid * RSH + NRBF] = __float2half_rn(1.0f);
        const float* rsrc = r_ij + (long)ba * TT * NRBF;
        for (int i = tid; i < TRBF; i += NTHREADS) {
            const int t = i / NRBF, r = i - t * NRBF;
            sRbfH[t * RSH + r] = __float2half_rn(rsrc[i]);
        }
        if (tid < TILT) {
            const long p = (long)ba * TT + tid;
            sMask[tid] = pmask[p];
            sNj[tid] = nj[p];
            sNk[tid] = nk[p];
        }
    }
    __syncthreads();

    float4 acc0 = make_float4(0.f, 0.f, 0.f, 0.f);
    float4 acc1 = make_float4(0.f, 0.f, 0.f, 0.f);

    for (int tile = 0; tile < NTIL; ++tile) {
        const int cur = tile & 1;
        const int nxt = cur ^ 1;

        float C[2][4][4];
#pragma unroll
        for (int mt = 0; mt < 2; ++mt)
#pragma unroll
            for (int j = 0; j < 4; ++j)
#pragma unroll
                for (int q = 0; q < 4; ++q) C[mt][j][q] = 0.0f;

        // ---- GEMM1 (bf1 folded via k=25 bias column) ----
#pragma unroll
        for (int ks = 0; ks < 2; ++ks) {
            uint32_t A[2][4];
            ldmat4(A[0], addrR[0] + ks * 32);
            ldmat4(A[1], addrR[1] + ks * 32);
#pragma unroll
            for (int mt = 0; mt < 2; ++mt)
#pragma unroll
                for (int j = 0; j < 4; ++j)
                    mma16(C[mt][j], A[mt], w1b[ks][2 * j], w1b[ks][2 * j + 1]);
        }

        // ---- ssp (fp32 poly) -> sH ----
#pragma unroll
        for (int mt = 0; mt < 2; ++mt)
#pragma unroll
            for (int j = 0; j < 4; ++j) {
                const int f0 = wn * 32 + j * 8 + l4 * 2;
                const int r0 = mbase + mt * 16 + gid;
                *(__half2*)(sHh + r0 * HSH + f0) = ssp2(C[mt][j][0], C[mt][j][1]);
                *(__half2*)(sHh + (r0 + 8) * HSH + f0) = ssp2(C[mt][j][2], C[mt][j][3]);
            }

        // ---- prefetch next tile into registers ----
        float rstg[7];
        float stg_mk = 0.0f; int stg_j = 0, stg_k = 0;
        if (tile < NTIL - 1) {
            const float* rnext = r_ij + ((long)ba * TT + (tile + 1) * TILT) * NRBF;
#pragma unroll
            for (int q = 0; q < 7; ++q) {
                const int i = tid + q * NTHREADS;
                if (i < TRBF) rstg[q] = rnext[i];
            }
            if (tid < TILT) {
                const long p = (long)ba * TT + (tile + 1) * TILT + tid;
                stg_mk = pmask[p];
                stg_j = nj[p];
                stg_k = nk[p];
            }
        }
        __syncthreads();   // sync1: sH visible

        // ---- GEMM2 ----
#pragma unroll
        for (int mt = 0; mt < 2; ++mt)
#pragma unroll
            for (int j = 0; j < 4; ++j)
#pragma unroll
                for (int q = 0; q < 4; ++q) C[mt][j][q] = 0.0f;
#pragma unroll
        for (int ks = 0; ks < 8; ++ks) {
            uint32_t A[2][4];
            ldmat4(A[0], addrH[0] + ks * 32);
            ldmat4(A[1], addrH[1] + ks * 32);
            const uint4* rowp = (const uint4*)sW2p + (ks * 32 + lane) * 8;
            uint4 q0 = rowp[nb4 ^ (lane & 7)];
            uint4 q1 = rowp[(nb4 + 1) ^ (lane & 7)];
            uint32_t bu[8] = {q0.x, q0.y, q0.z, q0.w, q1.x, q1.y, q1.z, q1.w};
#pragma unroll
            for (int mt = 0; mt < 2; ++mt)
#pragma unroll
                for (int j = 0; j < 4; ++j)
                    mma16(C[mt][j], A[mt], bu[2 * j], bu[2 * j + 1]);
        }

        // ---- store (C + bf2) * mask as fp16 -> W buffer[cur] ----
        {
            __half* wb = sWh + cur * WBUF;
#pragma unroll
            for (int mt = 0; mt < 2; ++mt) {
                const int t0 = mbase + mt * 16 + gid;
                const float m0 = sMask[cur * TILT + t0];
                const float m1 = sMask[cur * TILT + t0 + 8];
#pragma unroll
                for (int j = 0; j < 4; ++j) {
                    const int f0 = wn * 32 + j * 8 + l4 * 2;
                    const float2 b2 = *(const float2*)(sBf2 + f0);
                    *(__half2*)(wb + t0 * WSH + f0) =
                        __floats2half2_rn((C[mt][j][0] + b2.x) * m0,
                                          (C[mt][j][1] + b2.y) * m0);
                    *(__half2*)(wb + (t0 + 8) * WSH + f0) =
                        __floats2half2_rn((C[mt][j][2] + b2.x) * m1,
                                          (C[mt][j][3] + b2.y) * m1);
                }
            }
        }

        // ---- store staged tile ----
        if (tile < NTIL - 1) {
#pragma unroll
            for (int q = 0; q < 7; ++q) {
                const int i = tid + q * NTHREADS;
                if (i < TRBF) {
                    const int t = i / NRBF, r = i - t * NRBF;
                    sRbfH[t * RSH + r] = __float2half_rn(rstg[q]);
                }
            }
            if (tid < TILT) {
                sMask[nxt * TILT + tid] = stg_mk;
                sNj[nxt * TILT + tid] = stg_j;
                sNk[nxt * TILT + tid] = stg_k;
            }
        }
        __syncthreads();   // sync2

        // ---- row-coalesced epilogue, fp16 y (2 wf/row), 2 acc chains ----
        {
            const __half* wb = sWh + cur * WBUF;
#pragma unroll
            for (int r = 0; r < 8; r += 2) {
#pragma unroll
                for (int h = 0; h < 2; ++h) {
                    const int t = wid * 8 + r + h;
                    const uint2 yju = *(const uint2*)(Yb + sNj[cur * TILT + t] * NF + f4);
                    const uint2 yku = *(const uint2*)(Yb + sNk[cur * TILT + t] * NF + f4);
                    const float2 ja = __half22float2(*(const __half2*)&yju.x);
                    const float2 jb = __half22float2(*(const __half2*)&yju.y);
                    const float2 ka = __half22float2(*(const __half2*)&yku.x);
                    const float2 kb = __half22float2(*(const __half2*)&yku.y);
                    const uint2 wu = *(const uint2*)(wb + t * WSH + f4);
                    const float2 wlo = __half22float2(*(const __half2*)&wu.x);
                    const float2 whi = __half22float2(*(const __half2*)&wu.y);
                    float4& av = h ? acc1 : acc0;
                    av.x = fmaf(wlo.x, ja.x * ka.x, av.x);
                    av.y = fmaf(wlo.y, ja.y * ka.y, av.y);
                    av.z = fmaf(whi.x, jb.x * kb.x, av.z);
                    av.w = fmaf(whi.y, jb.y * kb.y, av.w);
                }
            }
        }
    }

    __syncthreads();
    // ---- cross-warp reduce ----
    {
        float4 accv = make_float4(acc0.x + acc1.x, acc0.y + acc1.y,
                                  acc0.z + acc1.z, acc0.w + acc1.w);
        *(float4*)(sPart + wid * NF + f4) = accv;
    }
    __syncthreads();
    if (tid < NF) {
        float s = 0.0f;
#pragma unroll
        for (int w = 0; w < 8; ++w) s += sPart[w * NF + tid];
        sY[tid] = s;
    }
    __syncthreads();

    // ---- f2out ----
    {
        const int o = tid & 127;
        const int q = tid >> 7;
        float s = 0.0f;
        const float* Wp = Wout + q * 64 * NF + o;
#pragma unroll 8
        for (int f = 0; f < 64; ++f) s += sY[q * 64 + f] * Wp[f * NF];
        sRed[q * NF + o] = s;
    }
    __syncthreads();
    if (tid < NF)
        out[(long)ba * NF + tid] = ssp(sRed[tid] + sRed[NF + tid] + bout[tid]);
}

// ---------------------------------------------------------------------------
extern "C" void kernel_launch(void* const* d_in, const int* in_sizes, int n_in,
                              void* d_out, int out_size) {
    const float* x    = (const float*)d_in[0];
    const float* r_ij = (const float*)d_in[1];
    const float* mask = (const float*)d_in[2];
    const float* Wf1  = (const float*)d_in[3];
    const float* bf1  = (const float*)d_in[4];
    const float* Wf2  = (const float*)d_in[5];
    const float* bf2  = (const float*)d_in[6];
    const float* Win  = (const float*)d_in[7];
    const float* Wout = (const float*)d_in[8];
    const float* bout = (const float*)d_in[9];
    const int*   nj   = (const int*)d_in[10];
    const int*   nk   = (const int*)d_in[11];
    float* out = (float*)d_out;

    prep_in2f_kernel<<<296, 256>>>(x, Win, Wf1, Wf2, bf1);

    cudaFuncSetAttribute(cfconv_mma,
                         cudaFuncAttributeMaxDynamicSharedMemorySize, SMEM_BYTES);
    dim3 grid(AA, BB);
    cfconv_mma<<<grid, NTHREADS, SMEM_BYTES>>>(r_ij, mask, bf2,
                                               Wout, bout, nj, nk, out);
}